// round 5
// baseline (speedup 1.0000x reference)
#include <cuda_runtime.h>
#include <math.h>

// Problem dims (fixed by setup_inputs): B=4, T=8192, D=512, H=512
#define BB 4
#define TT 8192
#define DD 512
#define HH 512
#define NC 64            // scan chunks along T
#define CL (TT / NC)     // 128 steps per chunk

// Scratch (static device globals: allocation-free contract)
__device__ float2 g_cv[(size_t)BB * TT * HH];   // (c, v) per (b,t,h)  — 128 MB
__device__ float2 g_agg[BB * NC * HH];          // chunk aggregates (C, V)
__device__ float  g_pref[BB * NC * HH];         // per-chunk incoming log_h prefix

typedef unsigned long long u64;

// Packed fp32x2 FMA (Blackwell FFMA2 — only reachable via PTX)
__device__ __forceinline__ void ffma2(u64 &d, u64 a, u64 b) {
    asm("fma.rn.f32x2 %0, %1, %2, %0;" : "+l"(d) : "l"(a), "l"(b));
}
__device__ __forceinline__ float2 u2f(u64 v) {
    float2 r;
    asm("mov.b64 {%0, %1}, %2;" : "=f"(r.x), "=f"(r.y) : "l"(v));
    return r;
}

// -softplus(k) = -(max(k,0) + log1p(exp(-|k|)))
__device__ __forceinline__ float neg_softplus(float k) {
    float e = __expf(-fabsf(k));
    return -(fmaxf(k, 0.0f) + __logf(1.0f + e));
}
// log g(p): p>=0 -> log(p+0.5); p<0 -> log(sigmoid(p)) = p - log1p(exp(p))
__device__ __forceinline__ float log_g(float p) {
    float e = __expf(-fabsf(p));
    return (p >= 0.0f) ? __logf(p + 0.5f) : (p - __logf(1.0f + e));
}
// logaddexp; safe when exactly one argument is -inf (other stays finite)
__device__ __forceinline__ float laddexp(float a, float b) {
    float mx = fmaxf(a, b);
    float e  = __expf(-fabsf(a - b));
    return mx + __logf(1.0f + e);
}

// ============================================================================
// Kernel 1: fused dual GEMM (k = x·Wz^T, p = x·Wh^T) + transform epilogue
//   Block tile: 128 rows (m) x 64 h-columns, computing BOTH k and p tiles
//   (128 logical columns: cols [0,64) = Wz rows h0..h0+63, [64,128) = Wh).
//   256 threads, 8x8 outputs/thread via packed fp32x2 FMA, double-buffered smem.
// ============================================================================
__global__ __launch_bounds__(256, 2) void gemm_cv_kernel(
    const float* __restrict__ x,
    const float* __restrict__ Wh, const float* __restrict__ bh,
    const float* __restrict__ Wz, const float* __restrict__ bz)
{
    __shared__ __align__(16) float2 As[2][8][128];  // duplicated (a,a) pairs, [k][m]
    __shared__ __align__(16) float  Bs[2][8][132];  // [k][logical col], padded

    const int tid = threadIdx.x;
    const int h0 = blockIdx.x * 64;
    const int m0 = blockIdx.y * 128;

    // ---- loader mapping: 128 rows x 2 k-halves of 4 floats ----
    const int lr = tid & 127;
    const int kh = tid >> 7;  // 0/1 -> k offset 0/4
    const float4* ap = reinterpret_cast<const float4*>(x + (size_t)(m0 + lr) * DD) + kh;
    const float* wrow = (lr < 64) ? (Wz + (size_t)(h0 + lr) * DD)
                                  : (Wh + (size_t)(h0 + lr - 64) * DD);
    const float4* bp = reinterpret_cast<const float4*>(wrow) + kh;

    // preload K-chunk 0
    {
        float4 xa = ap[0];
        float4 wb = bp[0];
        const float* xf = (const float*)&xa;
        const float* wf = (const float*)&wb;
        #pragma unroll
        for (int j = 0; j < 4; j++) {
            As[0][kh * 4 + j][lr] = make_float2(xf[j], xf[j]);
            Bs[0][kh * 4 + j][lr] = wf[j];
        }
    }
    __syncthreads();

    const int ty = tid >> 4;   // 0..15 -> rows ty*8 .. ty*8+7
    const int tx = tid & 15;   // cols 2*tx + 32*jp, jp=0..3

    u64 acc[8][4];
    #pragma unroll
    for (int i = 0; i < 8; i++)
        #pragma unroll
        for (int j = 0; j < 4; j++) acc[i][j] = 0ull;

    const int nsteps = DD / 8;  // 64
    for (int s = 0; s < nsteps; s++) {
        const int cb = s & 1;
        float4 xan, wbn;
        if (s + 1 < nsteps) {
            xan = ap[(s + 1) * 2];
            wbn = bp[(s + 1) * 2];
        }
        #pragma unroll
        for (int kk = 0; kk < 8; kk++) {
            u64 b2[4], a2[8];
            #pragma unroll
            for (int jp = 0; jp < 4; jp++)
                b2[jp] = *reinterpret_cast<const u64*>(&Bs[cb][kk][32 * jp + 2 * tx]);
            #pragma unroll
            for (int i = 0; i < 8; i++)
                a2[i] = *reinterpret_cast<const u64*>(&As[cb][kk][ty * 8 + i]);
            #pragma unroll
            for (int i = 0; i < 8; i++)
                #pragma unroll
                for (int jp = 0; jp < 4; jp++)
                    ffma2(acc[i][jp], a2[i], b2[jp]);
        }
        if (s + 1 < nsteps) {
            const int nb = cb ^ 1;
            const float* xf = (const float*)&xan;
            const float* wf = (const float*)&wbn;
            #pragma unroll
            for (int j = 0; j < 4; j++) {
                As[nb][kh * 4 + j][lr] = make_float2(xf[j], xf[j]);
                Bs[nb][kh * 4 + j][lr] = wf[j];
            }
        }
        __syncthreads();
    }

    // ---- fused epilogue: thread holds k (jp 0,1) and p (jp 2,3) for same h ----
    float bzv[2][2], bhv[2][2];
    #pragma unroll
    for (int hp = 0; hp < 2; hp++) {
        int h = h0 + 32 * hp + 2 * tx;
        bzv[hp][0] = bz[h];     bzv[hp][1] = bz[h + 1];
        bhv[hp][0] = bh[h];     bhv[hp][1] = bh[h + 1];
    }
    #pragma unroll
    for (int i = 0; i < 8; i++) {
        const size_t row = (size_t)(m0 + ty * 8 + i);   // flattened (b*T + t)
        #pragma unroll
        for (int hp = 0; hp < 2; hp++) {
            int h = h0 + 32 * hp + 2 * tx;
            float2 kp = u2f(acc[i][hp]);
            float2 pp = u2f(acc[i][hp + 2]);
            float k0 = kp.x + bzv[hp][0], k1 = kp.y + bzv[hp][1];
            float p0 = pp.x + bhv[hp][0], p1 = pp.y + bhv[hp][1];
            float c0 = neg_softplus(k0), c1 = neg_softplus(k1);
            float v0 = k0 + c0 + log_g(p0);   // log_z + log_tilde_h
            float v1 = k1 + c1 + log_g(p1);
            float4 o = make_float4(c0, v0, c1, v1);
            *reinterpret_cast<float4*>(&g_cv[row * HH + h]) = o;
        }
    }
}

// ============================================================================
// Kernel 2: per-chunk scan partials. lane = h (coalesced 256B/warp loads).
//   (C,V) := (C + c_t, logaddexp(V + c_t, v_t)), init (0, -inf).
// ============================================================================
__global__ void scan_partial_kernel()
{
    int gt = blockIdx.x * blockDim.x + threadIdx.x;  // BB*NC*HH threads
    int h     = gt & (HH - 1);
    int rest  = gt >> 9;            // / HH
    int chunk = rest & (NC - 1);
    int b     = rest >> 6;          // / NC
    const float2* p = g_cv + ((size_t)b * TT + (size_t)chunk * CL) * HH + h;
    float C = 0.0f, V = -INFINITY;
    #pragma unroll 4
    for (int t = 0; t < CL; t++) {
        float2 e = p[(size_t)t * HH];
        C += e.x;
        V = laddexp(V + e.x, e.y);
    }
    g_agg[gt] = make_float2(C, V);
}

// ============================================================================
// Kernel 3: scan chunk aggregates per (b,h), seeded with log(h_prev).
//   prefix[j] = log_h entering chunk j;  M := logaddexp(M + C_j, V_j)
// ============================================================================
__global__ void scan_carry_kernel(const float* __restrict__ hprev)
{
    int gt = blockIdx.x * blockDim.x + threadIdx.x;  // BB*HH threads
    int h = gt & (HH - 1);
    int b = gt >> 9;
    float M = __logf(hprev[(size_t)b * HH + h]);
    #pragma unroll 4
    for (int j = 0; j < NC; j++) {
        size_t idx = ((size_t)b * NC + j) * HH + h;
        g_pref[idx] = M;
        float2 a = g_agg[idx];
        M = laddexp(M + a.x, a.y);
    }
}

// ============================================================================
// Kernel 4: apply — rescan each chunk from its prefix, write h = exp(log_h).
// ============================================================================
__global__ void scan_apply_kernel(float* __restrict__ out)
{
    int gt = blockIdx.x * blockDim.x + threadIdx.x;
    int h     = gt & (HH - 1);
    int rest  = gt >> 9;
    int chunk = rest & (NC - 1);
    int b     = rest >> 6;
    float m = g_pref[gt];
    size_t base = ((size_t)b * TT + (size_t)chunk * CL) * HH + h;
    const float2* p = g_cv + base;
    float* o = out + base;
    #pragma unroll 4
    for (int t = 0; t < CL; t++) {
        float2 e = p[(size_t)t * HH];
        m = laddexp(m + e.x, e.y);
        o[(size_t)t * HH] = __expf(m);
    }
}

// ============================================================================
extern "C" void kernel_launch(void* const* d_in, const int* in_sizes, int n_in,
                              void* d_out, int out_size)
{
    (void)in_sizes; (void)n_in; (void)out_size;
    const float* x  = (const float*)d_in[0];   // (B,T,D)
    const float* hp = (const float*)d_in[1];   // (B,1,H)
    const float* Wh = (const float*)d_in[2];   // (H,D)
    const float* bh = (const float*)d_in[3];   // (H,)
    const float* Wz = (const float*)d_in[4];   // (H,D)
    const float* bz = (const float*)d_in[5];   // (H,)
    float* out = (float*)d_out;                // (B,T,H) fp32

    // GEMM: grid.x = h-tiles (fast dim) so concurrent blocks share x rows in L2
    dim3 gg(HH / 64, (BB * TT) / 128);
    gemm_cv_kernel<<<gg, 256>>>(x, Wh, bh, Wz, bz);
    scan_partial_kernel<<<(BB * NC * HH) / 256, 256>>>();
    scan_carry_kernel<<<(BB * HH) / 256, 256>>>(hp);
    scan_apply_kernel<<<(BB * NC * HH) / 256, 256>>>(out);
}

// round 7
// speedup vs baseline: 1.9823x; 1.9823x over previous
#include <cuda_runtime.h>
#include <cuda_bf16.h>
#include <math.h>
#include <stdint.h>

// Problem dims (fixed): B=4, T=8192, D=512, H=512
#define BB 4
#define TT 8192
#define DD 512
#define HH 512
#define NC 64
#define CL (TT / NC)
#define MROWS (BB * TT)      // 32768 flattened rows

// ---------------- scratch (allocation-free contract) ----------------
__device__ __align__(16) float2 g_cv[(size_t)BB * TT * HH];        // 128 MB
__device__ float2 g_agg[BB * NC * HH];
__device__ float  g_pref[BB * NC * HH];
__device__ __align__(16) __nv_bfloat16 g_xhi[(size_t)MROWS * DD];  // 32 MB
__device__ __align__(16) __nv_bfloat16 g_xlo[(size_t)MROWS * DD];  // 32 MB
__device__ __align__(16) __nv_bfloat16 g_bhi[(size_t)1024 * DD];   // packed: row R -> (R&1? Wh : Wz)[R>>1]
__device__ __align__(16) __nv_bfloat16 g_blo[(size_t)1024 * DD];

// ---------------- helpers ----------------
__device__ __forceinline__ uint32_t smem_u32(const void* p) {
    uint32_t a;
    asm("{ .reg .u64 t; cvta.to.shared.u64 t, %1; cvt.u32.u64 %0, t; }" : "=r"(a) : "l"(p));
    return a;
}
__device__ __forceinline__ void cpasync16(uint32_t dst, const void* src) {
    asm volatile("cp.async.cg.shared.global [%0], [%1], 16;" :: "r"(dst), "l"(src));
}
__device__ __forceinline__ void ldsm_x4(uint32_t* r, uint32_t addr) {
    asm volatile("ldmatrix.sync.aligned.m8n8.x4.shared.b16 {%0,%1,%2,%3}, [%4];"
                 : "=r"(r[0]), "=r"(r[1]), "=r"(r[2]), "=r"(r[3]) : "r"(addr));
}
__device__ __forceinline__ void mma_bf16(float* c, const uint32_t* a, const uint32_t* b) {
    asm volatile(
        "mma.sync.aligned.m16n8k16.row.col.f32.bf16.bf16.f32 "
        "{%0,%1,%2,%3}, {%4,%5,%6,%7}, {%8,%9}, {%0,%1,%2,%3};"
        : "+f"(c[0]), "+f"(c[1]), "+f"(c[2]), "+f"(c[3])
        : "r"(a[0]), "r"(a[1]), "r"(a[2]), "r"(a[3]), "r"(b[0]), "r"(b[1]));
}

// ---------------- math ----------------
__device__ __forceinline__ float neg_softplus(float k) {
    float e = __expf(-fabsf(k));
    return -(fmaxf(k, 0.0f) + __logf(1.0f + e));
}
__device__ __forceinline__ float log_g(float p) {
    float e = __expf(-fabsf(p));
    return (p >= 0.0f) ? __logf(p + 0.5f) : (p - __logf(1.0f + e));
}
__device__ __forceinline__ float laddexp(float a, float b) {
    float mx = fmaxf(a, b);
    float e  = __expf(-fabsf(a - b));
    return mx + __logf(1.0f + e);
}

// ============================================================================
// Pre-convert: x (fp32) -> hi/lo bf16
// ============================================================================
__global__ void convert_x_kernel(const float* __restrict__ x)
{
    size_t i = (size_t)blockIdx.x * 256 + threadIdx.x;   // one float4 per thread
    float4 v = reinterpret_cast<const float4*>(x)[i];
    float f[4] = {v.x, v.y, v.z, v.w};
    unsigned long long uh = 0, ul = 0;
    #pragma unroll
    for (int j = 0; j < 4; j++) {
        __nv_bfloat16 hi = __float2bfloat16(f[j]);
        __nv_bfloat16 lo = __float2bfloat16(f[j] - __bfloat162float(hi));
        uh |= (unsigned long long)__bfloat16_as_ushort(hi) << (16 * j);
        ul |= (unsigned long long)__bfloat16_as_ushort(lo) << (16 * j);
    }
    reinterpret_cast<unsigned long long*>(g_xhi)[i] = uh;
    reinterpret_cast<unsigned long long*>(g_xlo)[i] = ul;
}

// Pack weights interleaved: row R -> (R odd ? Wh : Wz)[R>>1], hi/lo split.
__global__ void pack_w_kernel(const float* __restrict__ Wh, const float* __restrict__ Wz)
{
    int R = blockIdx.x;
    int t = threadIdx.x;            // 128 threads, 4 cols each
    const float* src = (R & 1) ? (Wh + (size_t)(R >> 1) * DD) : (Wz + (size_t)(R >> 1) * DD);
    float4 v = *reinterpret_cast<const float4*>(src + t * 4);
    float f[4] = {v.x, v.y, v.z, v.w};
    unsigned long long uh = 0, ul = 0;
    #pragma unroll
    for (int q = 0; q < 4; q++) {
        __nv_bfloat16 hi = __float2bfloat16(f[q]);
        __nv_bfloat16 lo = __float2bfloat16(f[q] - __bfloat162float(hi));
        uh |= (unsigned long long)__bfloat16_as_ushort(hi) << (16 * q);
        ul |= (unsigned long long)__bfloat16_as_ushort(lo) << (16 * q);
    }
    reinterpret_cast<unsigned long long*>(g_bhi)[(size_t)R * 128 + t] = uh;
    reinterpret_cast<unsigned long long*>(g_blo)[(size_t)R * 128 + t] = ul;
}

// ============================================================================
// bf16 mma.sync GEMM, 3-split folded into K'=1536 (48 chunks of 32):
//   seg0: xhi*bhi, seg1: xlo*bhi, seg2: xhi*blo
// CTA tile 128x128; 8 warps (4x2), warp tile 32x64; 4-stage cp.async pipeline.
// Smem row stride 80B => conflict-free ldmatrix without swizzle.
// ============================================================================
#define RSTRIDE 80
#define STAGE_A 10240            // 128 rows * 80
#define STAGE_BYTES 20480        // A + B
#define SMEM_TOTAL (4 * STAGE_BYTES)   // 81920

__device__ __forceinline__ void load_chunk(uint32_t sb, int tid, int m0, int j, int cc)
{
    const int seg = cc >> 4;
    const int k0  = (cc & 15) * 32;
    const __nv_bfloat16* As = (seg == 1) ? g_xlo : g_xhi;
    const __nv_bfloat16* Bs = (seg == 2) ? g_blo : g_bhi;
    uint32_t base = sb + (cc & 3) * STAGE_BYTES;
    #pragma unroll
    for (int q = 0; q < 4; q++) {
        int idx = q * 256 + tid;                 // 0..1023
        int r   = (idx >> 2) & 127;
        int c16 = idx & 3;
        uint32_t dst = base + (idx >> 9) * STAGE_A + r * RSTRIDE + c16 * 16;
        const __nv_bfloat16* src = (idx < 512)
            ? As + (size_t)(m0 + r) * DD + k0 + c16 * 8
            : Bs + (size_t)(j * 128 + r) * DD + k0 + c16 * 8;
        cpasync16(dst, src);
    }
}

__global__ __launch_bounds__(256, 2) void gemm_mma_kernel(
    const float* __restrict__ bh, const float* __restrict__ bz)
{
    extern __shared__ char smem[];
    uint32_t sb = smem_u32(smem);
    const int tid  = threadIdx.x;
    const int lane = tid & 31;
    const int wid  = tid >> 5;
    const int wm   = wid & 3;        // warp row (0..3) -> m offset wm*32
    const int wn   = wid >> 2;       // warp col (0..1) -> n offset wn*64
    const int j    = blockIdx.x;     // n-tile: packed cols [j*128, j*128+128)
    const int m0   = blockIdx.y * 128;

    float acc[2][8][4];
    #pragma unroll
    for (int tm = 0; tm < 2; tm++)
        #pragma unroll
        for (int nt = 0; nt < 8; nt++)
            #pragma unroll
            for (int e = 0; e < 4; e++) acc[tm][nt][e] = 0.0f;

    // prologue: stages 0..2
    #pragma unroll
    for (int s = 0; s < 3; s++) {
        load_chunk(sb, tid, m0, j, s);
        asm volatile("cp.async.commit_group;" ::: "memory");
    }

    const int arow = (lane & 7) + ((lane >> 3) & 1) * 8;   // A ldmatrix row
    const int akh  = lane >> 4;                            // A k-half
    const int bnr  = ((lane >> 4) << 3) + (lane & 7);      // B ldmatrix n-row
    const int bkh  = (lane >> 3) & 1;                      // B k-half

    for (int cc = 0; cc < 48; cc++) {
        asm volatile("cp.async.wait_group 2;" ::: "memory");
        __syncthreads();
        if (cc + 3 < 48) load_chunk(sb, tid, m0, j, cc + 3);
        asm volatile("cp.async.commit_group;" ::: "memory");

        uint32_t abase = sb + (cc & 3) * STAGE_BYTES + wm * 32 * RSTRIDE;
        uint32_t bbase = sb + (cc & 3) * STAGE_BYTES + STAGE_A + wn * 64 * RSTRIDE;

        #pragma unroll
        for (int kk = 0; kk < 2; kk++) {
            uint32_t a[2][4];
            #pragma unroll
            for (int tm = 0; tm < 2; tm++)
                ldsm_x4(a[tm], abase + (tm * 16 + arow) * RSTRIDE + kk * 32 + akh * 16);
            uint32_t b[8][2];
            #pragma unroll
            for (int g = 0; g < 4; g++) {
                uint32_t r4[4];
                ldsm_x4(r4, bbase + (g * 16 + bnr) * RSTRIDE + kk * 32 + bkh * 16);
                b[2 * g][0] = r4[0]; b[2 * g][1] = r4[1];
                b[2 * g + 1][0] = r4[2]; b[2 * g + 1][1] = r4[3];
            }
            #pragma unroll
            for (int tm = 0; tm < 2; tm++)
                #pragma unroll
                for (int nt = 0; nt < 8; nt++)
                    mma_bf16(acc[tm][nt], a[tm], b[nt]);
        }
    }

    // ---- fused epilogue: c-frag pairs (even,odd col) = (k, p) for one h ----
    float bzr[8], bhr[8];
    #pragma unroll
    for (int nt = 0; nt < 8; nt++) {
        int h = (j * 128 + wn * 64 + nt * 8 + (lane & 3) * 2) >> 1;
        bzr[nt] = bz[h];
        bhr[nt] = bh[h];
    }
    #pragma unroll
    for (int tm = 0; tm < 2; tm++) {
        int r0 = m0 + wm * 32 + tm * 16 + (lane >> 2);
        #pragma unroll
        for (int nt = 0; nt < 8; nt++) {
            int h = (j * 128 + wn * 64 + nt * 8 + (lane & 3) * 2) >> 1;
            float k0 = acc[tm][nt][0] + bzr[nt];
            float p0 = acc[tm][nt][1] + bhr[nt];
            float c0 = neg_softplus(k0);
            g_cv[(size_t)r0 * HH + h] = make_float2(c0, k0 + c0 + log_g(p0));
            float k1 = acc[tm][nt][2] + bzr[nt];
            float p1 = acc[tm][nt][3] + bhr[nt];
            float c1 = neg_softplus(k1);
            g_cv[(size_t)(r0 + 8) * HH + h] = make_float2(c1, k1 + c1 + log_g(p1));
        }
    }
}

// ============================================================================
// Scan kernels (HBM-bound, unchanged)
// ============================================================================
__global__ void scan_partial_kernel()
{
    int gt = blockIdx.x * blockDim.x + threadIdx.x;
    int h     = gt & (HH - 1);
    int rest  = gt >> 9;
    int chunk = rest & (NC - 1);
    int b     = rest >> 6;
    const float2* p = g_cv + ((size_t)b * TT + (size_t)chunk * CL) * HH + h;
    float C = 0.0f, V = -INFINITY;
    #pragma unroll 4
    for (int t = 0; t < CL; t++) {
        float2 e = p[(size_t)t * HH];
        C += e.x;
        V = laddexp(V + e.x, e.y);
    }
    g_agg[gt] = make_float2(C, V);
}

__global__ void scan_carry_kernel(const float* __restrict__ hprev)
{
    int gt = blockIdx.x * blockDim.x + threadIdx.x;
    int h = gt & (HH - 1);
    int b = gt >> 9;
    float M = __logf(hprev[(size_t)b * HH + h]);
    #pragma unroll 4
    for (int j = 0; j < NC; j++) {
        size_t idx = ((size_t)b * NC + j) * HH + h;
        g_pref[idx] = M;
        float2 a = g_agg[idx];
        M = laddexp(M + a.x, a.y);
    }
}

__global__ void scan_apply_kernel(float* __restrict__ out)
{
    int gt = blockIdx.x * blockDim.x + threadIdx.x;
    int h     = gt & (HH - 1);
    int rest  = gt >> 9;
    int chunk = rest & (NC - 1);
    int b     = rest >> 6;
    float m = g_pref[gt];
    size_t base = ((size_t)b * TT + (size_t)chunk * CL) * HH + h;
    const float2* p = g_cv + base;
    float* o = out + base;
    #pragma unroll 4
    for (int t = 0; t < CL; t++) {
        float2 e = p[(size_t)t * HH];
        m = laddexp(m + e.x, e.y);
        o[(size_t)t * HH] = __expf(m);
    }
}

// ============================================================================
extern "C" void kernel_launch(void* const* d_in, const int* in_sizes, int n_in,
                              void* d_out, int out_size)
{
    (void)in_sizes; (void)n_in; (void)out_size;
    const float* x  = (const float*)d_in[0];
    const float* hp = (const float*)d_in[1];
    const float* Wh = (const float*)d_in[2];
    const float* bh = (const float*)d_in[3];
    const float* Wz = (const float*)d_in[4];
    const float* bz = (const float*)d_in[5];
    float* out = (float*)d_out;

    cudaFuncSetAttribute(gemm_mma_kernel, cudaFuncAttributeMaxDynamicSharedMemorySize, SMEM_TOTAL);

    convert_x_kernel<<<(MROWS * DD / 4) / 256, 256>>>(x);
    pack_w_kernel<<<1024, 128>>>(Wh, Wz);
    gemm_mma_kernel<<<dim3(8, 256), 256, SMEM_TOTAL>>>(bh, bz);
    scan_partial_kernel<<<(BB * NC * HH) / 256, 256>>>();
    scan_carry_kernel<<<(BB * HH) / 256, 256>>>(hp);
    scan_apply_kernel<<<(BB * NC * HH) / 256, 256>>>(out);
}